// round 11
// baseline (speedup 1.0000x reference)
#include <cuda_runtime.h>
#include <cuda_fp16.h>
#include <cstdint>

// Problem constants
#define BB   64
#define NN   100
#define DD   32
#define E0   96
#define E1   160
#define E2   192
#define NODES (BB*NN)          // 6400
#define ROWS  (BB*NN*NN)       // 640000
#define TIL   64
#define NTILES (ROWS/TIL)      // 10000
#define GRID_E 304

// ---------------- scratch ----------------
__device__ __align__(16) float    g_u[NODES*E0];
__device__ __align__(16) float    g_v[NODES*E0];
__device__ __align__(16) float    g_agg[NODES*E2];
__device__ __align__(16) uint32_t g_w1h[6*20*64];    // 7680
__device__ __align__(16) uint32_t g_w2h[10*24*64];   // 15360
__device__ __align__(16) uint32_t g_nw0h[14*32*64];  // 28672
__device__ __align__(16) uint32_t g_nw1h[16*32*64];  // 32768
__device__ __align__(16) uint32_t g_nw2h[16*4*64];   // 4096

__device__ __forceinline__ float lrelu(float x){ return x > 0.f ? x : 0.2f*x; }

__device__ __forceinline__ uint32_t h2pack(float a, float b){
    __half2 h = __floats2half2_rn(a, b);
    return *(uint32_t*)&h;
}

// ---------------- cp.async ----------------
#define CP_ASYNC16(smem_u32, gptr) \
    asm volatile("cp.async.cg.shared.global [%0], [%1], 16;" :: "r"((uint32_t)(smem_u32)), "l"(gptr) : "memory")
#define CP_COMMIT() asm volatile("cp.async.commit_group;" ::: "memory")
#define CP_WAIT0()  asm volatile("cp.async.wait_group 0;" ::: "memory")

__device__ __forceinline__ uint32_t smem_to_u32(const void* p){
    uint32_t a;
    asm("{ .reg .u64 t; cvta.to.shared.u64 t, %1; cvt.u32.u64 %0, t; }" : "=r"(a) : "l"(p));
    return a;
}

// ---------------- mma.sync m16n8k16 fp16 (fp32 accum) ----------------
__device__ __forceinline__ void mma16(float c[4], const uint32_t a[4], const uint32_t b[2]){
    asm volatile("mma.sync.aligned.m16n8k16.row.col.f32.f16.f16.f32 "
        "{%0,%1,%2,%3}, {%4,%5,%6,%7}, {%8,%9}, {%0,%1,%2,%3};"
        : "+f"(c[0]), "+f"(c[1]), "+f"(c[2]), "+f"(c[3])
        : "r"(a[0]), "r"(a[1]), "r"(a[2]), "r"(a[3]), "r"(b[0]), "r"(b[1]));
}

__device__ __forceinline__ void ldsm4(uint32_t r[4], uint32_t addr){
    asm volatile("ldmatrix.sync.aligned.m8n8.x4.shared.b16 {%0,%1,%2,%3}, [%4];"
        : "=r"(r[0]), "=r"(r[1]), "=r"(r[2]), "=r"(r[3]) : "r"(addr));
}

__device__ __forceinline__ float redg(float v){
    v += __shfl_xor_sync(0xFFFFFFFFu, v, 4);
    v += __shfl_xor_sync(0xFFFFFFFFu, v, 8);
    v += __shfl_xor_sync(0xFFFFFFFFu, v, 16);
    return v;
}

// ---------------------------------------------------------------------------
// prep: fused w_prep (blocks 0..345) + node_pre (blocks 346..6745)
// ---------------------------------------------------------------------------
__device__ __forceinline__ void packW(uint32_t* dst, const float* W, int N, int NT, int idx){
    const int ks  = idx / (NT*64);
    const int rem = idx - ks*(NT*64);
    const int nt  = rem >> 6;
    const int l2  = rem & 63;
    const int lane = l2 >> 1, r = l2 & 1;
    const int gg = lane >> 2, tg = lane & 3;
    const int k0 = ks*16 + 2*tg + 8*r;
    const int n  = nt*8 + gg;
    dst[idx] = h2pack(W[k0*N + n], W[(k0+1)*N + n]);
}

#define WPREP_BLOCKS 346   // 346*256 = 88576 exactly

__global__ void prep(const float* __restrict__ x,
                     const float* __restrict__ w0, const float* __restrict__ b0,
                     const float* __restrict__ w1, const float* __restrict__ w2,
                     const float* __restrict__ nw0, const float* __restrict__ nw1,
                     const float* __restrict__ nw2)
{
    const int t = threadIdx.x;
    if (blockIdx.x < WPREP_BLOCKS) {
        const int idx = blockIdx.x * 256 + t;
        if      (idx < 7680)        packW(g_w1h,  w1,  E1,  20, idx);
        else if (idx < 23040)       packW(g_w2h,  w2,  E2,  24, idx - 7680);
        else if (idx < 51712)       packW(g_nw0h, nw0, 256, 32, idx - 23040);
        else if (idx < 84480)       packW(g_nw1h, nw1, 256, 32, idx - 51712);
        else                        packW(g_nw2h, nw2, 32,  4,  idx - 84480);
        return;
    }
    __shared__ float sx[DD];
    const int node = blockIdx.x - WPREP_BLOCKS;
    if (t < E2) g_agg[node*E2 + t] = 0.f;
    if (t < DD) sx[t] = x[node*DD + t];
    __syncthreads();
    if (t < E2) {
        float acc = 0.f;
        if (t < E0) {
            const int c = t;
            #pragma unroll
            for (int k = 0; k < DD; k++) acc += sx[k] * w0[k*E0 + c];
            g_u[node*E0 + c] = acc + b0[c];
        } else {
            const int c = t - E0;
            #pragma unroll
            for (int k = 0; k < DD; k++) acc += sx[k] * w0[(DD+k)*E0 + c];
            g_v[node*E0 + c] = acc;
        }
    }
}

// ---------------------------------------------------------------------------
// edge_kernel: persistent, 128 threads = 4 warps, each warp is a pure
// n-slice computing ALL 64 rows (mt=4) x its 40/48-col slice.
// -> every B-fragment loaded exactly once per CTA (half of R7's traffic)
// -> columns warp-exclusive: segmented reduce ends in-warp, atomics direct.
// smem words: region [0,5376): H0 (stride 52) / H1 (stride 84, aliases)
//             sW1 @5376 (7680) | sW2 @13056 (15360) = 28416 w = 113664 B
// 2 CTAs/SM. 4 barriers/tile (4-warp barriers).
// ---------------------------------------------------------------------------
#define H0S 52
#define H1S 84
#define SW1W 5376
#define SW2W 13056
#define EDGE_WORDS 28416
#define EDGE_SMEM_BYTES (EDGE_WORDS*4)

__global__ __launch_bounds__(128, 2)
void edge_kernel(const float* __restrict__ b1v, const float* __restrict__ b2v)
{
    extern __shared__ uint32_t smem_u[];
    uint32_t* sW1 = smem_u + SW1W;
    uint32_t* sW2 = smem_u + SW2W;
    __shared__ float sB[352];                      // b1[160] | b2[192]

    const int tid  = threadIdx.x;
    const int w    = tid >> 5;                     // n-slice 0..3
    const int lane = tid & 31;
    const int g    = lane >> 2;
    const int tg   = lane & 3;

    const int lrow = lane & 15;
    const int lcol = (lane >> 4) * 4;
    const uint32_t regB = smem_to_u32(smem_u);
    // per-mt ldmatrix base addresses
    uint32_t aH0[4], aH1[4];
    #pragma unroll
    for (int mt = 0; mt < 4; mt++) {
        aH0[mt] = regB + (((mt*16 + lrow)*H0S) + lcol)*4;
        aH1[mt] = regB + (((mt*16 + lrow)*H1S) + lcol)*4;
    }

    // ---- preload weights + biases once ----
    {
        const uint32_t s1 = smem_to_u32(sW1);
        for (int i = tid; i < 1920; i += 128) CP_ASYNC16(s1 + i*16, (const void*)(g_w1h + i*4));
        const uint32_t s2 = smem_to_u32(sW2);
        for (int i = tid; i < 3840; i += 128) CP_ASYNC16(s2 + i*16, (const void*)(g_w2h + i*4));
        CP_COMMIT();
        for (int i = tid; i < 160; i += 128) sB[i]       = __ldg(b1v + i);
        for (int i = tid; i < 192; i += 128) sB[160 + i] = __ldg(b2v + i);
        CP_WAIT0();
    }
    __syncthreads();

    // hoisted biases for this warp's slices
    float bb1[5][2], bb2[6][2];
    #pragma unroll
    for (int nt = 0; nt < 5; nt++) {
        const int col = w*40 + nt*8 + 2*tg;
        bb1[nt][0] = sB[col];
        bb1[nt][1] = sB[col + 1];
    }
    #pragma unroll
    for (int nt = 0; nt < 6; nt++) {
        const int col = w*48 + nt*8 + 2*tg;
        bb2[nt][0] = sB[160 + col];
        bb2[nt][1] = sB[160 + col + 1];
    }

    for (int tile = blockIdx.x; tile < NTILES; tile += GRID_E) {
        const int base = tile * TIL;

        // ---- build H0 = fp16(lrelu(u_i + v_j)) -> [row][52w] ----
        // 128 threads: 2 threads/row, each packs 48 halves (12 float4 -> 24 words)
        {
            const int row = tid >> 1;
            const int kh  = tid & 1;
            const int R   = base + row;
            const int nu  = R / 100;
            const int nv  = (R / 10000) * 100 + (R - nu*100);
            const float4* up = (const float4*)(g_u + nu*E0) + kh*12;
            const float4* vp = (const float4*)(g_v + nv*E0) + kh*12;
            uint32_t* dst = smem_u + row*H0S + kh*24;
            #pragma unroll
            for (int i = 0; i < 12; i++) {
                const float4 uu = up[i];
                const float4 vv = vp[i];
                uint2 wv;
                wv.x = h2pack(lrelu(uu.x + vv.x), lrelu(uu.y + vv.y));
                wv.y = h2pack(lrelu(uu.z + vv.z), lrelu(uu.w + vv.w));
                *(uint2*)(dst + i*2) = wv;
            }
        }
        __syncthreads();                           // (1) H0 ready

        // ---- GEMM1: C1[64 x 40-slice] per warp ----
        float c1[4][5][4];
        #pragma unroll
        for (int mt = 0; mt < 4; mt++)
            #pragma unroll
            for (int nt = 0; nt < 5; nt++)
                #pragma unroll
                for (int e = 0; e < 4; e++) c1[mt][nt][e] = 0.f;

        #pragma unroll
        for (int ks = 0; ks < 6; ks++) {
            uint32_t a[4][4];
            #pragma unroll
            for (int mt = 0; mt < 4; mt++) ldsm4(a[mt], aH0[mt] + ks*32);
            #pragma unroll
            for (int nt = 0; nt < 5; nt++) {
                uint32_t b[2];
                *(uint2*)b = *(const uint2*)&sW1[((ks*20 + w*5 + nt)*32 + lane)*2];
                #pragma unroll
                for (int mt = 0; mt < 4; mt++) mma16(c1[mt][nt], a[mt], b);
            }
        }
        __syncthreads();                           // (2) H0 reads done (H1 aliases)

        // ---- epilogue1: H1 = fp16(lrelu(C1 + b1)) -> [row][84w] ----
        #pragma unroll
        for (int nt = 0; nt < 5; nt++) {
            const int cw = (w*40 + nt*8 + 2*tg) >> 1;   // word index (col/2)
            #pragma unroll
            for (int mt = 0; mt < 4; mt++) {
                const int r0 = mt*16 + g;
                smem_u[r0*H1S + cw]     = h2pack(lrelu(c1[mt][nt][0] + bb1[nt][0]), lrelu(c1[mt][nt][1] + bb1[nt][1]));
                smem_u[(r0+8)*H1S + cw] = h2pack(lrelu(c1[mt][nt][2] + bb1[nt][0]), lrelu(c1[mt][nt][3] + bb1[nt][1]));
            }
        }
        __syncthreads();                           // (3) H1 ready

        // ---- GEMM2: C2[64 x 48-slice] per warp ----
        float c2[4][6][4];
        #pragma unroll
        for (int mt = 0; mt < 4; mt++)
            #pragma unroll
            for (int nt = 0; nt < 6; nt++)
                #pragma unroll
                for (int e = 0; e < 4; e++) c2[mt][nt][e] = 0.f;

        #pragma unroll
        for (int ks = 0; ks < 10; ks++) {
            uint32_t a[4][4];
            #pragma unroll
            for (int mt = 0; mt < 4; mt++) ldsm4(a[mt], aH1[mt] + ks*32);
            #pragma unroll
            for (int nt = 0; nt < 6; nt++) {
                uint32_t b[2];
                *(uint2*)b = *(const uint2*)&sW2[((ks*24 + w*6 + nt)*32 + lane)*2];
                #pragma unroll
                for (int mt = 0; mt < 4; mt++) mma16(c2[mt][nt], a[mt], b);
            }
        }

        // ---- epilogue2 + full in-warp segmented reduce (cols warp-exclusive) ----
        const int s0 = base / 100;
        const int r1 = (s0 + 1)*100 - base;        // boundary row in (0,100]

        float acc[2][12];
        #pragma unroll
        for (int s = 0; s < 2; s++)
            #pragma unroll
            for (int i = 0; i < 12; i++) acc[s][i] = 0.f;

        #pragma unroll
        for (int nt = 0; nt < 6; nt++) {
            #pragma unroll
            for (int mt = 0; mt < 4; mt++) {
                const int rA = mt*16 + g;
                const int rB = rA + 8;
                const int sA = (rA >= r1);
                const int sB = (rB >= r1);
                acc[sA][nt*2  ] += lrelu(c2[mt][nt][0] + bb2[nt][0]);
                acc[sA][nt*2+1] += lrelu(c2[mt][nt][1] + bb2[nt][1]);
                acc[sB][nt*2  ] += lrelu(c2[mt][nt][2] + bb2[nt][0]);
                acc[sB][nt*2+1] += lrelu(c2[mt][nt][3] + bb2[nt][1]);
            }
        }
        const bool two = (r1 < TIL);
        #pragma unroll
        for (int i = 0; i < 12; i++) {
            acc[0][i] = redg(acc[0][i]);
            if (two) acc[1][i] = redg(acc[1][i]);
        }
        if (lane < 4) {                            // g==0 lanes hold totals
            #pragma unroll
            for (int nt = 0; nt < 6; nt++) {
                const int col = w*48 + nt*8 + 2*lane;
                atomicAdd(&g_agg[s0*E2 + col],     acc[0][nt*2]);
                atomicAdd(&g_agg[s0*E2 + col + 1], acc[0][nt*2+1]);
                if (two) {
                    atomicAdd(&g_agg[(s0+1)*E2 + col],     acc[1][nt*2]);
                    atomicAdd(&g_agg[(s0+1)*E2 + col + 1], acc[1][nt*2+1]);
                }
            }
        }
        __syncthreads();                           // (4) H1 reads done before next build
    }
}

// ---------------------------------------------------------------------------
// node_mlp: fp16 mma + ldmatrix, 32 rows/CTA (two 16-row halves), grid=200,
// block=256. smem: bufA [32][132w] + bufB [32][132w]
// ---------------------------------------------------------------------------
#define NBS 132
#define NODE_SMEM_BYTES (2*32*NBS*4)

__global__ __launch_bounds__(256)
void node_mlp(const float* __restrict__ x,
              const float* __restrict__ b0,
              const float* __restrict__ b1,
              const float* __restrict__ b2,
              float* __restrict__ out)
{
    extern __shared__ uint32_t smem_u[];
    uint32_t* bufA = smem_u;
    uint32_t* bufB = smem_u + 32*NBS;

    const int tid  = threadIdx.x;
    const int warp = tid >> 5;
    const int lane = tid & 31;
    const int g    = lane >> 2;
    const int tg   = lane & 3;
    const int half = warp >> 2;
    const int wq   = warp & 3;
    const int base = blockIdx.x * 32;

    const int lrow = lane & 15;
    const int lcol = (lane >> 4) * 4;
    const uint32_t aA = smem_to_u32(bufA) + ((half*16 + lrow)*NBS + lcol)*4;
    const uint32_t aB = smem_to_u32(bufB) + ((half*16 + lrow)*NBS + lcol)*4;

    for (int i = tid; i < 32*112; i += 256) {
        const int row = i / 112;
        const int kw  = i - row*112;
        const int k   = kw*2;
        const int node = base + row;
        float v0, v1;
        if (k < E2) { v0 = g_agg[node*E2 + k]; v1 = g_agg[node*E2 + k + 1]; }
        else        { v0 = x[node*DD + (k - E2)]; v1 = x[node*DD + (k - E2) + 1]; }
        bufA[row*NBS + kw] = h2pack(v0, v1);
    }
    __syncthreads();

    for (int layer = 0; layer < 2; layer++) {
        const uint32_t aIn  = layer ? aB : aA;
        uint32_t* sOut      = layer ? bufA : bufB;
        const uint32_t* wpk = layer ? g_nw1h : g_nw0h;
        const float* bias   = layer ? b1 : b0;
        const int nks       = layer ? 16 : 14;

        float c[8][4];
        #pragma unroll
        for (int nt = 0; nt < 8; nt++)
            #pragma unroll
            for (int e = 0; e < 4; e++) c[nt][e] = 0.f;

        for (int ks = 0; ks < nks; ks++) {
            uint32_t a[4];
            ldsm4(a, aIn + ks*32);
            #pragma unroll
            for (int nt = 0; nt < 8; nt++) {
                uint32_t b[2];
                *(uint2*)b = *(const uint2*)&wpk[((ks*32 + wq*8 + nt)*32 + lane)*2];
                mma16(c[nt], a, b);
            }
        }
        __syncthreads();
        #pragma unroll
        for (int nt = 0; nt < 8; nt++) {
            const int col = wq*64 + nt*8 + 2*tg;
            const float ba = __ldg(bias + col);
            const float bb = __ldg(bias + col + 1);
            const int r0 = half*16 + g;
            sOut[r0*NBS + (col>>1)]     = h2pack(lrelu(c[nt][0] + ba), lrelu(c[nt][1] + bb));
            sOut[(r0+8)*NBS + (col>>1)] = h2pack(lrelu(c[nt][2] + ba), lrelu(c[nt][3] + bb));
        }
        __syncthreads();
    }

    {
        float c3[4] = {0.f, 0.f, 0.f, 0.f};
        for (int ks = 0; ks < 16; ks++) {
            uint32_t a[4];
            ldsm4(a, aA + ks*32);
            uint32_t b[2];
            *(uint2*)b = *(const uint2*)&g_nw2h[((ks*4 + wq)*32 + lane)*2];
            mma16(c3, a, b);
        }
        const int col = wq*8 + 2*tg;
        const float ba = __ldg(b2 + col);
        const float bb = __ldg(b2 + col + 1);
        float2 lo = {c3[0] + ba, c3[1] + bb};
        float2 hi = {c3[2] + ba, c3[3] + bb};
        const int r0 = base + half*16 + g;
        *(float2*)&out[r0*32 + col]       = lo;
        *(float2*)&out[(r0 + 8)*32 + col] = hi;
    }
}

// ---------------------------------------------------------------------------
extern "C" void kernel_launch(void* const* d_in, const int* in_sizes, int n_in,
                              void* d_out, int out_size)
{
    const float* x     = (const float*)d_in[0];
    const float* fe_w0 = (const float*)d_in[1];
    const float* fe_b0 = (const float*)d_in[2];
    const float* fe_w1 = (const float*)d_in[3];
    const float* fe_b1 = (const float*)d_in[4];
    const float* fe_w2 = (const float*)d_in[5];
    const float* fe_b2 = (const float*)d_in[6];
    const float* fn_w0 = (const float*)d_in[7];
    const float* fn_b0 = (const float*)d_in[8];
    const float* fn_w1 = (const float*)d_in[9];
    const float* fn_b1 = (const float*)d_in[10];
    const float* fn_w2 = (const float*)d_in[11];
    const float* fn_b2 = (const float*)d_in[12];
    float* out = (float*)d_out;

    cudaFuncSetAttribute(edge_kernel, cudaFuncAttributeMaxDynamicSharedMemorySize, EDGE_SMEM_BYTES);
    cudaFuncSetAttribute(node_mlp,    cudaFuncAttributeMaxDynamicSharedMemorySize, NODE_SMEM_BYTES);

    prep<<<WPREP_BLOCKS + NODES, 256>>>(x, fe_w0, fe_b0, fe_w1, fe_w2, fn_w0, fn_w1, fn_w2);
    edge_kernel<<<GRID_E, 128, EDGE_SMEM_BYTES>>>(fe_b1, fe_b2);
    node_mlp<<<NODES/32, 256, NODE_SMEM_BYTES>>>(x, fn_b0, fn_b1, fn_b2, out);
}